// round 6
// baseline (speedup 1.0000x reference)
#include <cuda_runtime.h>
#include <math.h>

#define Vv 500000
#define Ee 128
#define Hh 128
#define Ll 10
#define Pp 10
#define Nn 50
#define Bb 61            // 1 + P + N
#define Gg 384           // 3*H gate outputs

// ---- packed fp32x2 helpers (sm_100+; ptxas never auto-emits FFMA2) ----
#define FMA_F32X2(d, a, b, c) \
    asm("fma.rn.f32x2 %0, %1, %2, %3;" : "=l"(d) : "l"(a), "l"(b), "l"(c))
#define PACK_F32X2(out, lo, hi) \
    asm("mov.b64 %0, {%1, %2};" : "=l"(out) : "r"(lo), "r"(hi))
#define UNPACK_F32X2(lo, hi, in) \
    asm("mov.b64 {%0, %1}, %2;" : "=r"(lo), "=r"(hi) : "l"(in))

// Scratch (no allocation allowed)
__device__ float2 g_wih2[Ee * Gg];        // [k][g] = (w_ih[g][k], w_ih[g][k]) duplicated
__device__ float2 g_whh2[(Hh / 2) * Gg];  // [k2][g] = (w_hh[g][2k2], w_hh[g][2k2+1])
__device__ float  g_enc[Bb * Hh];
__device__ unsigned int g_ticket;         // reset by prep each call; prep->gru is
                                          // stream-ordered inside the captured graph,
                                          // so replays are deterministic.

// ---------------------------------------------------------------------------
// Kernel 1: repack weights + reset completion ticket.
//   g_wih2 : k-major, value duplicated into both b64 lanes (direct FFMA2 src)
//   g_whh2 : k-pair-major float2 (coalesced b64 per-thread register fills)
// ---------------------------------------------------------------------------
__global__ void prep_kernel(const float* __restrict__ w_ih,
                            const float* __restrict__ w_hh) {
    int idx = blockIdx.x * blockDim.x + threadIdx.x;
    if (idx == 0) g_ticket = 0u;
    if (idx < Ee * Gg) {
        int k = idx % Ee;                 // coalesced read of w_ih
        int g = idx / Ee;
        float w = w_ih[g * Ee + k];
        g_wih2[k * Gg + g] = make_float2(w, w);
    } else if (idx < Ee * Gg + (Hh / 2) * Gg) {
        int j  = idx - Ee * Gg;
        int g  = j % Gg;                  // coalesced write of g_whh2
        int k2 = j / Gg;
        g_whh2[k2 * Gg + g] =
            make_float2(w_hh[g * Hh + 2 * k2], w_hh[g * Hh + 2 * k2 + 1]);
    }
}

// ---------------------------------------------------------------------------
// Kernel 2: fused gather + batched input projection + serial GRU recurrence
// + (in the last-finishing block) the final loss reduction.
// One block per sequence (61 blocks), 384 threads (thread g = gate output g).
// ---------------------------------------------------------------------------
__global__ void __launch_bounds__(Gg, 1) gru_kernel(
    const int* __restrict__ phr,
    const int* __restrict__ pos,
    const int* __restrict__ neg,
    const float* __restrict__ u_emb,
    const float* __restrict__ v_emb,
    const float* __restrict__ b_ih,
    const float* __restrict__ b_hh,
    const float* __restrict__ h0,
    float* __restrict__ out)
{
    __shared__ __align__(16) float x_s[Ee][12];   // [k][l], 48B row stride
    __shared__ float s_gi[Ll][Gg];
    __shared__ float s_gh[Gg];
    __shared__ __align__(16) float h_buf[2][Hh];  // double-buffered hidden state
    __shared__ float node_s[Hh];
    __shared__ float d_s[Bb - 1];
    __shared__ unsigned int my_ticket;

    const int b = blockIdx.x;
    const int g = threadIdx.x;

    // ---- gather x[l][:] for all 10 steps (coalesced 128B per row-chunk) ----
    for (int i = g; i < Ll * Ee; i += Gg) {
        int l = i / Ee;
        int e = i % Ee;
        int row;
        const float* src;
        if (b == 0)          { row = phr[l];                     src = u_emb; }
        else if (b <= Pp)    { row = pos[(b - 1) * Ll + l];      src = v_emb; }
        else                 { row = neg[(b - 1 - Pp) * Ll + l]; src = v_emb; }
        x_s[e][l] = src[row * Ee + e];
    }
    if (g < Hh) h_buf[0][g] = h0[g];
    __syncthreads();

    // ---- phase 1: gi[l][g] = b_ih[g] + sum_k w_ih[g][k] * x[l][k] ----
    // 5 packed accumulators cover l = (0,1)..(8,9); x pairs are adjacent in
    // smem (b64 loads), w comes pre-duplicated as a b64 from g_wih2.
    // unroll 8 guarantees >=8 outstanding w2 LDGs (hides ~250cyc L2 latency
    // with only 3 warps/SMSP resident).
    const float bi = b_ih[g];
    unsigned long long acc2[5];
    {
        unsigned long long bi2;
        PACK_F32X2(bi2, __float_as_uint(bi), __float_as_uint(bi));
#pragma unroll
        for (int j = 0; j < 5; j++) acc2[j] = bi2;
    }
    {
        const unsigned long long* wp =
            reinterpret_cast<const unsigned long long*>(g_wih2);
#pragma unroll 8
        for (int k = 0; k < Ee; k++) {
            unsigned long long w2 = wp[k * Gg + g];   // coalesced b64, L2-resident
            const unsigned long long* xr =
                reinterpret_cast<const unsigned long long*>(&x_s[k][0]);
            FMA_F32X2(acc2[0], w2, xr[0], acc2[0]);
            FMA_F32X2(acc2[1], w2, xr[1], acc2[1]);
            FMA_F32X2(acc2[2], w2, xr[2], acc2[2]);
            FMA_F32X2(acc2[3], w2, xr[3], acc2[3]);
            FMA_F32X2(acc2[4], w2, xr[4], acc2[4]);
        }
    }
#pragma unroll
    for (int j = 0; j < 5; j++) {
        unsigned int lo, hi;
        UNPACK_F32X2(lo, hi, acc2[j]);
        s_gi[2 * j][g]     = __uint_as_float(lo);
        s_gi[2 * j + 1][g] = __uint_as_float(hi);
    }

    // ---- pull this thread's w_hh row into 64 packed b64 registers ----
    unsigned long long wreg2[Hh / 2];
    {
        const unsigned long long* wsrc =
            reinterpret_cast<const unsigned long long*>(g_whh2);
#pragma unroll
        for (int k2 = 0; k2 < Hh / 2; k2++)
            wreg2[k2] = wsrc[k2 * Gg + g];            // coalesced b64
    }
    const float bh = b_hh[g];
    __syncthreads();

    // ---- phase 2: serial recurrence, double-buffered h, 2 BARs/step ----
    float hlast = 0.0f;
#pragma unroll 1
    for (int l = 0; l < Ll; l++) {
        const int cur = l & 1, nxt = cur ^ 1;
        const unsigned long long* hp =
            reinterpret_cast<const unsigned long long*>(h_buf[cur]);
        unsigned long long a0, a1, a2, a3;            // 4 chains: dep depth 16
        PACK_F32X2(a0, 0u, 0u);
        a1 = a0; a2 = a0; a3 = a0;
#pragma unroll
        for (int k2 = 0; k2 < Hh / 2; k2 += 4) {
            FMA_F32X2(a0, wreg2[k2],     hp[k2],     a0);
            FMA_F32X2(a1, wreg2[k2 + 1], hp[k2 + 1], a1);
            FMA_F32X2(a2, wreg2[k2 + 2], hp[k2 + 2], a2);
            FMA_F32X2(a3, wreg2[k2 + 3], hp[k2 + 3], a3);
        }
        unsigned int x0, y0, x1, y1, x2, y2, x3, y3;
        UNPACK_F32X2(x0, y0, a0);
        UNPACK_F32X2(x1, y1, a1);
        UNPACK_F32X2(x2, y2, a2);
        UNPACK_F32X2(x3, y3, a3);
        s_gh[g] = bh +
            ((__uint_as_float(x0) + __uint_as_float(y0)) +
             (__uint_as_float(x1) + __uint_as_float(y1))) +
            ((__uint_as_float(x2) + __uint_as_float(y2)) +
             (__uint_as_float(x3) + __uint_as_float(y3)));
        // BAR 1: s_gh visible; all reads of h_buf[cur] complete.
        __syncthreads();
        if (g < Hh) {
            float ir = s_gi[l][g], iz = s_gi[l][Hh + g], in_ = s_gi[l][2 * Hh + g];
            float hr = s_gh[g],    hz = s_gh[Hh + g],    hn  = s_gh[2 * Hh + g];
            float r = 1.0f / (1.0f + expf(-(ir + hr)));
            float z = 1.0f / (1.0f + expf(-(iz + hz)));
            float n = tanhf(in_ + r * hn);
            hlast = (1.0f - z) * n + z * h_buf[cur][g];
            h_buf[nxt][g] = hlast;                    // distinct buffer: safe
        }
        // BAR 2: h_buf[nxt] visible for next step's matvec.
        __syncthreads();
    }

    if (g < Hh) g_enc[b * Hh + g] = hlast;

    // ---- completion ticket: last-finishing block computes the loss ----
    __threadfence();                                   // release: g_enc visible
    __syncthreads();                                   // all lanes' STGs issued
    if (g == 0) my_ticket = atomicAdd(&g_ticket, 1u);
    __syncthreads();
    if (my_ticket != Bb - 1) return;
    __threadfence();                                   // acquire: order g_enc reads
                                                       // after the ticket observation

    // ---- loss tail (one block, 12 warps): 60 warp-reduced dot products ----
    const int lane = g & 31;
    const int w    = g >> 5;

    if (g < Hh) node_s[g] = g_enc[g];
    __syncthreads();

    for (int i = w; i < Bb - 1; i += Gg / 32) {
        const float* e = &g_enc[(i + 1) * Hh];
        float s = 0.0f;
#pragma unroll
        for (int c = 0; c < Hh / 32; c++)
            s += node_s[lane + 32 * c] * e[lane + 32 * c];
#pragma unroll
        for (int off = 16; off; off >>= 1)
            s += __shfl_xor_sync(0xffffffffu, s, off);
        if (lane == 0) d_s[i] = s;
    }
    __syncthreads();

    if (g == 0) {
        const float inv_h = 1.0f / (float)Hh;
        float pos_loss = 0.0f;
        for (int i = 0; i < Pp; i++)
            pos_loss += d_s[i] * inv_h;
        float neg_sum = 0.0f;
        for (int i = Pp; i < Bb - 1; i++) {
            float s = d_s[i] * inv_h;
            if (s > 0.0f) neg_sum += expf(s);
        }
        // reference: -( -log(1+neg_sum) + pos_loss )
        out[0] = logf(1.0f + neg_sum) - pos_loss;
    }
}

// ---------------------------------------------------------------------------
extern "C" void kernel_launch(void* const* d_in, const int* in_sizes, int n_in,
                              void* d_out, int out_size) {
    const int*   phr   = (const int*)  d_in[0];
    const int*   pos   = (const int*)  d_in[1];
    const int*   neg   = (const int*)  d_in[2];
    const float* u_emb = (const float*)d_in[3];
    const float* v_emb = (const float*)d_in[4];
    const float* w_ih  = (const float*)d_in[5];
    const float* w_hh  = (const float*)d_in[6];
    const float* b_ih  = (const float*)d_in[7];
    const float* b_hh  = (const float*)d_in[8];
    const float* h0    = (const float*)d_in[9];

    const int prep_threads = Ee * Gg + (Hh / 2) * Gg;   // 73728
    prep_kernel<<<(prep_threads + 255) / 256, 256>>>(w_ih, w_hh);
    gru_kernel<<<Bb, Gg>>>(phr, pos, neg, u_emb, v_emb, b_ih, b_hh, h0,
                           (float*)d_out);
}

// round 8
// speedup vs baseline: 1.0118x; 1.0118x over previous
#include <cuda_runtime.h>
#include <math.h>

#define Ee 128
#define Hh 128
#define Ll 10
#define Pp 10
#define Nn 50
#define Bb 61            // 1 + P + N
#define Gg 384           // 3*H gate outputs
#define KH 64            // k half-size for the split projection

typedef unsigned long long ull;

// ---- packed fp32x2 helpers (sm_100+; ptxas never auto-emits FFMA2) ----
#define FMA_F32X2(d, a, b, c) \
    asm("fma.rn.f32x2 %0, %1, %2, %3;" : "=l"(d) : "l"(a), "l"(b), "l"(c))
#define PACK_F32X2(out, lo, hi) \
    asm("mov.b64 %0, {%1, %2};" : "=l"(out) : "r"(lo), "r"(hi))
#define UNPACK_F32X2(lo, hi, in) \
    asm("mov.b64 {%0, %1}, %2;" : "=r"(lo), "=r"(hi) : "l"(in))

// Scratch (no allocation allowed)
__device__ float2 g_wih2[Ee * Gg];        // [k][g] = (w_ih[g][k], w_ih[g][k]) duplicated
__device__ float2 g_whh2[(Hh / 2) * Gg];  // [k2][g] = (w_hh[g][2k2], w_hh[g][2k2+1])
__device__ float  g_giH[2][Bb][Ll][Gg];   // k-half partial input projections
__device__ float  g_enc[Bb * Hh];
__device__ unsigned int g_ticket;         // reset by prep each call (stream-ordered
                                          // inside the graph -> replay-deterministic)

// ---------------------------------------------------------------------------
// Kernel 1: repack weights + reset completion ticket.
// ---------------------------------------------------------------------------
__global__ void prep_kernel(const float* __restrict__ w_ih,
                            const float* __restrict__ w_hh) {
    int idx = blockIdx.x * blockDim.x + threadIdx.x;
    if (idx == 0) g_ticket = 0u;
    if (idx < Ee * Gg) {
        int k = idx % Ee;                 // coalesced read of w_ih
        int g = idx / Ee;
        float w = w_ih[g * Ee + k];
        g_wih2[k * Gg + g] = make_float2(w, w);
    } else if (idx < Ee * Gg + (Hh / 2) * Gg) {
        int j  = idx - Ee * Gg;
        int g  = j % Gg;                  // coalesced write of g_whh2
        int k2 = j / Gg;
        g_whh2[k2 * Gg + g] =
            make_float2(w_hh[g * Hh + 2 * k2], w_hh[g * Hh + 2 * k2 + 1]);
    }
}

// ---------------------------------------------------------------------------
// Kernel 2: gather + input projection, k-split across blockIdx.y.
// grid (61, 2) x 384 threads = 122 blocks (one full wave). Block (b, half)
// computes partial sums over k in [half*64, half*64+64) for all 10 steps.
// ---------------------------------------------------------------------------
__global__ void __launch_bounds__(Gg) gi_kernel(
    const int* __restrict__ phr,
    const int* __restrict__ pos,
    const int* __restrict__ neg,
    const float* __restrict__ u_emb,
    const float* __restrict__ v_emb)
{
    __shared__ __align__(16) float x_s[KH][12];   // [kk][l], 48B row stride

    const int b    = blockIdx.x;
    const int half = blockIdx.y;
    const int k0   = half * KH;
    const int g    = threadIdx.x;

    // ---- gather this half's slice of x[l][:] (coalesced 256B row chunks) ----
    for (int i = g; i < Ll * KH; i += Gg) {
        int l = i / KH;
        int e = i % KH;
        int row;
        const float* src;
        if (b == 0)          { row = phr[l];                     src = u_emb; }
        else if (b <= Pp)    { row = pos[(b - 1) * Ll + l];      src = v_emb; }
        else                 { row = neg[(b - 1 - Pp) * Ll + l]; src = v_emb; }
        x_s[e][l] = src[row * Ee + k0 + e];
    }
    __syncthreads();

    // ---- partial gi: sum over this k-half (bias added in the rec kernel) ----
    ull acc2[5];
    {
        ull z; PACK_F32X2(z, 0u, 0u);
#pragma unroll
        for (int j = 0; j < 5; j++) acc2[j] = z;
    }
    {
        const ull* wp = reinterpret_cast<const ull*>(g_wih2);
#pragma unroll 8
        for (int kk = 0; kk < KH; kk++) {
            ull w2 = wp[(k0 + kk) * Gg + g];          // coalesced b64, L2-resident
            const char* xrow = reinterpret_cast<const char*>(&x_s[kk][0]);
            ulonglong2 xa = *reinterpret_cast<const ulonglong2*>(xrow);      // l 0-3
            ulonglong2 xb = *reinterpret_cast<const ulonglong2*>(xrow + 16); // l 4-7
            ull        xc = *reinterpret_cast<const ull*>(xrow + 32);        // l 8-9
            FMA_F32X2(acc2[0], w2, xa.x, acc2[0]);
            FMA_F32X2(acc2[1], w2, xa.y, acc2[1]);
            FMA_F32X2(acc2[2], w2, xb.x, acc2[2]);
            FMA_F32X2(acc2[3], w2, xb.y, acc2[3]);
            FMA_F32X2(acc2[4], w2, xc,   acc2[4]);
        }
    }
    float* dst = &g_giH[half][b][0][0];
#pragma unroll
    for (int j = 0; j < 5; j++) {
        unsigned int lo, hi;
        UNPACK_F32X2(lo, hi, acc2[j]);
        dst[(2 * j)     * Gg + g] = __uint_as_float(lo);
        dst[(2 * j + 1) * Gg + g] = __uint_as_float(hi);
    }
}

// ---------------------------------------------------------------------------
// Kernel 3: serial GRU recurrence + (last-finishing block) loss reduction.
// 61 blocks x 384 threads (thread g = gate output g).
// ---------------------------------------------------------------------------
__global__ void __launch_bounds__(Gg, 1) rec_loss_kernel(
    const float* __restrict__ b_ih,
    const float* __restrict__ b_hh,
    const float* __restrict__ h0,
    float* __restrict__ out)
{
    __shared__ float s_gi[Ll][Gg];
    __shared__ float s_gh[Gg];
    __shared__ __align__(16) float h_buf[2][Hh];  // double-buffered hidden state
    __shared__ float node_s[Hh];
    __shared__ float d_s[Bb - 1];
    __shared__ unsigned int my_ticket;

    const int b = blockIdx.x;
    const int g = threadIdx.x;

    // ---- pull this thread's w_hh row into 64 packed b64 registers ----
    ull wreg2[Hh / 2];
    {
        const ull* wsrc = reinterpret_cast<const ull*>(g_whh2);
#pragma unroll
        for (int k2 = 0; k2 < Hh / 2; k2++)
            wreg2[k2] = wsrc[k2 * Gg + g];            // coalesced b64
    }

    // ---- preload gi: combine the two k-half partials + bias (20 batched LDGs) ----
    {
        const float bi = b_ih[g];
#pragma unroll
        for (int l = 0; l < Ll; l++)
            s_gi[l][g] = bi + g_giH[0][b][l][g] + g_giH[1][b][l][g];
    }

    const float bh = b_hh[g];
    if (g < Hh) h_buf[0][g] = h0[g];
    __syncthreads();

    // ---- serial recurrence, double-buffered h, 2 BARs/step ----
    float hlast = 0.0f;
#pragma unroll 1
    for (int l = 0; l < Ll; l++) {
        const int cur = l & 1, nxt = cur ^ 1;
        const ulonglong2* hp =
            reinterpret_cast<const ulonglong2*>(h_buf[cur]); // broadcast LDS.128
        ull a0, a1, a2, a3;                                  // 4 chains, depth 16
        PACK_F32X2(a0, 0u, 0u);
        a1 = a0; a2 = a0; a3 = a0;
#pragma unroll
        for (int q = 0; q < Hh / 4; q += 2) {
            ulonglong2 ha = hp[q];
            ulonglong2 hb = hp[q + 1];
            FMA_F32X2(a0, wreg2[2 * q],     ha.x, a0);
            FMA_F32X2(a1, wreg2[2 * q + 1], ha.y, a1);
            FMA_F32X2(a2, wreg2[2 * q + 2], hb.x, a2);
            FMA_F32X2(a3, wreg2[2 * q + 3], hb.y, a3);
        }
        unsigned int x0, y0, x1, y1, x2, y2, x3, y3;
        UNPACK_F32X2(x0, y0, a0);
        UNPACK_F32X2(x1, y1, a1);
        UNPACK_F32X2(x2, y2, a2);
        UNPACK_F32X2(x3, y3, a3);
        s_gh[g] = bh +
            ((__uint_as_float(x0) + __uint_as_float(y0)) +
             (__uint_as_float(x1) + __uint_as_float(y1))) +
            ((__uint_as_float(x2) + __uint_as_float(y2)) +
             (__uint_as_float(x3) + __uint_as_float(y3)));
        // BAR 1: s_gh visible; all reads of h_buf[cur] complete.
        __syncthreads();
        if (g < Hh) {
            float ir = s_gi[l][g], iz = s_gi[l][Hh + g], in_ = s_gi[l][2 * Hh + g];
            float hr = s_gh[g],    hz = s_gh[Hh + g],    hn  = s_gh[2 * Hh + g];
            float r = 1.0f / (1.0f + expf(-(ir + hr)));
            float z = 1.0f / (1.0f + expf(-(iz + hz)));
            float n = tanhf(in_ + r * hn);
            hlast = (1.0f - z) * n + z * h_buf[cur][g];
            h_buf[nxt][g] = hlast;                    // distinct buffer: safe
        }
        // BAR 2: h_buf[nxt] visible for next step's matvec.
        __syncthreads();
    }

    if (g < Hh) g_enc[b * Hh + g] = hlast;

    // ---- completion ticket: last-finishing block computes the loss ----
    __threadfence();                                   // release: g_enc visible
    __syncthreads();                                   // all lanes' STGs issued
    if (g == 0) my_ticket = atomicAdd(&g_ticket, 1u);
    __syncthreads();
    if (my_ticket != Bb - 1) return;
    __threadfence();                                   // acquire: order g_enc reads

    // ---- loss tail: 60 warp-reduced dot products, then warp-parallel combine ----
    const int lane = g & 31;
    const int w    = g >> 5;          // 12 warps

    if (g < Hh) node_s[g] = g_enc[g];
    __syncthreads();

    for (int i = w; i < Bb - 1; i += Gg / 32) {
        const float* e = &g_enc[(i + 1) * Hh];
        float s = 0.0f;
#pragma unroll
        for (int c = 0; c < Hh / 32; c++)
            s += node_s[lane + 32 * c] * e[lane + 32 * c];
#pragma unroll
        for (int off = 16; off; off >>= 1)
            s += __shfl_xor_sync(0xffffffffu, s, off);
        if (lane == 0) d_s[i] = s;
    }
    __syncthreads();

    if (w == 0) {
        const float inv_h = 1.0f / (float)Hh;
        // pos terms: lanes 0..9
        float pos = (lane < Pp) ? d_s[lane] * inv_h : 0.0f;
        // neg terms: i = 10+lane and 42+lane cover 10..59
        float neg = 0.0f;
        {
            int i = Pp + lane;
            if (i < Bb - 1) {
                float s = d_s[i] * inv_h;
                if (s > 0.0f) neg += expf(s);
            }
            i += 32;
            if (i < Bb - 1) {
                float s = d_s[i] * inv_h;
                if (s > 0.0f) neg += expf(s);
            }
        }
#pragma unroll
        for (int off = 16; off; off >>= 1) {
            pos += __shfl_xor_sync(0xffffffffu, pos, off);
            neg += __shfl_xor_sync(0xffffffffu, neg, off);
        }
        if (lane == 0)
            out[0] = logf(1.0f + neg) - pos;   // = -( -log(1+neg) + pos )
    }
}

// ---------------------------------------------------------------------------
extern "C" void kernel_launch(void* const* d_in, const int* in_sizes, int n_in,
                              void* d_out, int out_size) {
    const int*   phr   = (const int*)  d_in[0];
    const int*   pos   = (const int*)  d_in[1];
    const int*   neg   = (const int*)  d_in[2];
    const float* u_emb = (const float*)d_in[3];
    const float* v_emb = (const float*)d_in[4];
    const float* w_ih  = (const float*)d_in[5];
    const float* w_hh  = (const float*)d_in[6];
    const float* b_ih  = (const float*)d_in[7];
    const float* b_hh  = (const float*)d_in[8];
    const float* h0    = (const float*)d_in[9];

    const int prep_threads = Ee * Gg + (Hh / 2) * Gg;   // 73728
    prep_kernel<<<(prep_threads + 255) / 256, 256>>>(w_ih, w_hh);
    gi_kernel<<<dim3(Bb, 2), Gg>>>(phr, pos, neg, u_emb, v_emb);
    rec_loss_kernel<<<Bb, Gg>>>(b_ih, b_hh, h0, (float*)d_out);
}